// round 2
// baseline (speedup 1.0000x reference)
#include <cuda_runtime.h>

// NetVLAD fused pool, fp32x2 packed-FMA SIMT, sm_103a.
// Per CTA = (m, s): rows n in [s*512, s*512+512), processed in 4 tiles of 128.
//  Stage A: logits = Rtile @ W^T + b (FFMA2 paired across c) -> softmax -> Adup[n][k]={a,a}
//  Stage B: V[k][c] += a[n][k]*r[n][c] (FFMA2 paired across c), asum via ADD2
//  Epilogue: atomicAdd(out, V - asum*centroid); out zeroed by nv_zero.

#define FMA2(d, a, b, c) asm("fma.rn.f32x2 %0, %1, %2, %3;" : "=l"(d) : "l"(a), "l"(b), "l"(c))
#define ADD2(d, a, b)    asm("add.rn.f32x2 %0, %1, %2;"     : "=l"(d) : "l"(a), "l"(b))
#define PACK2(d, lo, hi) asm("mov.b64 %0, {%1, %2};"        : "=l"(d) : "f"(lo), "f"(hi))
#define UNPK2(lo, hi, s) asm("mov.b64 {%0, %1}, %2;"        : "=f"(lo), "=f"(hi) : "l"(s))

namespace {
typedef unsigned long long u64;
constexpr int BT    = 256;
constexpr int Nn    = 2048;
constexpr int Cc    = 64;
constexpr int Kk    = 32;
constexpr int SPLIT = 4;
constexpr int NT    = 128;
constexpr int TILES = (Nn / SPLIT) / NT;   // 4
constexpr int RP    = 68;   // Rrow pitch (floats)
constexpr int ADP   = 68;   // Adup pitch (floats): 32 float2 + pad
constexpr int WPP   = 68;   // Wp pitch (floats): 32 float2 + pad
constexpr int SMEM_BYTES = (NT * RP + NT * ADP + (Cc / 2) * WPP) * 4; // 78336
}

__global__ void nv_zero(float4* __restrict__ out, int n4) {
    int i = blockIdx.x * blockDim.x + threadIdx.x;
    if (i < n4) out[i] = make_float4(0.f, 0.f, 0.f, 0.f);
}

__global__ __launch_bounds__(256, 2) void nv_main(
    const float* __restrict__ R, const float* __restrict__ W,
    const float* __restrict__ bvec, const float* __restrict__ cent,
    float* __restrict__ out)
{
    extern __shared__ float sm[];
    float* Rrow = sm;                         // [NT][RP]  n-major R tile
    float* Adup = sm + NT * RP;               // [NT][ADP] dup softmax: {a,a} per k
    float* Wp   = sm + NT * RP + NT * ADP;    // [C/2][WPP] paired W: {w[c][k], w[c+1][k]}

    const int t = threadIdx.x;
    const int m = blockIdx.x >> 2;
    const int s = blockIdx.x & 3;

    // Build Wp: W is (K=32, C=64) row-major. Wp[c/2][k] float2 = {W[k][c], W[k][c+1]}
    #pragma unroll
    for (int i = 0; i < 8; i++) {
        int idx = i * 256 + t;               // idx = k*64 + c
        int k = idx >> 6, c = idx & 63;
        Wp[(c >> 1) * WPP + 2 * k + (c & 1)] = W[idx];
    }

    // ---- Stage A mapping: (ng 0..31, kg 0..7); rows ng+32*i, k = 4*kg+j
    const int kg = t & 7;
    const int ng = t >> 3;
    u64 biasp[4];
    {
        const float4 b4 = *reinterpret_cast<const float4*>(bvec + 4 * kg);
        PACK2(biasp[0], b4.x, 0.f);
        PACK2(biasp[1], b4.y, 0.f);
        PACK2(biasp[2], b4.z, 0.f);
        PACK2(biasp[3], b4.w, 0.f);
    }

    // ---- Stage B mapping: q = n-quarter, 4k x 8c tile
    const int q   = t >> 6;          // 0..3
    const int cg  = (t >> 3) & 7;    // c0 = 8*cg
    const int kg2 = t & 7;           // k0 = 4*kg2

    u64 accB[4][4];                  // [k][cpair] : lo=c even, hi=c odd of the pair
    u64 asum2[4];
    #pragma unroll
    for (int j = 0; j < 4; j++) {
        asum2[j] = 0ull;
        #pragma unroll
        for (int p = 0; p < 4; p++) accB[j][p] = 0ull;
    }

    const float* Rbase = R + ((size_t)m * Nn + (size_t)s * (Nn / SPLIT)) * Cc;

    for (int tile = 0; tile < TILES; ++tile) {
        __syncthreads();   // prior stage B done with Rrow/Adup

        // ---- Load R tile: 128x64 floats, coalesced float4
        const float4* Rg = reinterpret_cast<const float4*>(Rbase + (size_t)tile * NT * Cc);
        #pragma unroll
        for (int i = 0; i < 8; i++) {
            int idx = i * 256 + t;           // 0..2047 float4s
            float4 v = Rg[idx];
            *reinterpret_cast<float4*>(Rrow + (idx >> 4) * RP + (idx & 15) * 4) = v;
        }
        __syncthreads();

        // ---- Stage A: packed logits GEMM. acc lo/hi = even/odd-c partial sums.
        u64 accA[4][4];
        #pragma unroll
        for (int i = 0; i < 4; i++)
            #pragma unroll
            for (int j = 0; j < 4; j++) accA[i][j] = biasp[j];

        #pragma unroll
        for (int c0 = 0; c0 < Cc; c0 += 4) {
            const int cp0 = c0 >> 1;
            // wa/wb: k0..k3 at cpair cp0 ; wc/wd: k0..k3 at cpair cp0+1
            ulonglong2 wa = *reinterpret_cast<const ulonglong2*>(Wp + cp0 * WPP + 8 * kg);
            ulonglong2 wb = *reinterpret_cast<const ulonglong2*>(Wp + cp0 * WPP + 8 * kg + 4);
            ulonglong2 wc = *reinterpret_cast<const ulonglong2*>(Wp + (cp0 + 1) * WPP + 8 * kg);
            ulonglong2 wd = *reinterpret_cast<const ulonglong2*>(Wp + (cp0 + 1) * WPP + 8 * kg + 4);
            #pragma unroll
            for (int i = 0; i < 4; i++) {
                ulonglong2 r = *reinterpret_cast<const ulonglong2*>(Rrow + (ng + 32 * i) * RP + c0);
                FMA2(accA[i][0], r.x, wa.x, accA[i][0]);
                FMA2(accA[i][1], r.x, wa.y, accA[i][1]);
                FMA2(accA[i][2], r.x, wb.x, accA[i][2]);
                FMA2(accA[i][3], r.x, wb.y, accA[i][3]);
                FMA2(accA[i][0], r.y, wc.x, accA[i][0]);
                FMA2(accA[i][1], r.y, wc.y, accA[i][1]);
                FMA2(accA[i][2], r.y, wd.x, accA[i][2]);
                FMA2(accA[i][3], r.y, wd.y, accA[i][3]);
            }
        }

        // ---- Softmax per row across the 8 kg-lanes; write duplicated probs
        #pragma unroll
        for (int i = 0; i < 4; i++) {
            float l0, l1, l2, l3, lo, hi;
            UNPK2(lo, hi, accA[i][0]); l0 = lo + hi;
            UNPK2(lo, hi, accA[i][1]); l1 = lo + hi;
            UNPK2(lo, hi, accA[i][2]); l2 = lo + hi;
            UNPK2(lo, hi, accA[i][3]); l3 = lo + hi;
            float mx = fmaxf(fmaxf(l0, l1), fmaxf(l2, l3));
            mx = fmaxf(mx, __shfl_xor_sync(0xffffffffu, mx, 1));
            mx = fmaxf(mx, __shfl_xor_sync(0xffffffffu, mx, 2));
            mx = fmaxf(mx, __shfl_xor_sync(0xffffffffu, mx, 4));
            float e0 = __expf(l0 - mx);
            float e1 = __expf(l1 - mx);
            float e2 = __expf(l2 - mx);
            float e3 = __expf(l3 - mx);
            float ss = (e0 + e1) + (e2 + e3);
            ss += __shfl_xor_sync(0xffffffffu, ss, 1);
            ss += __shfl_xor_sync(0xffffffffu, ss, 2);
            ss += __shfl_xor_sync(0xffffffffu, ss, 4);
            float inv = __fdividef(1.f, ss);
            e0 *= inv; e1 *= inv; e2 *= inv; e3 *= inv;
            ulonglong2 s01, s23;
            PACK2(s01.x, e0, e0);
            PACK2(s01.y, e1, e1);
            PACK2(s23.x, e2, e2);
            PACK2(s23.y, e3, e3);
            float* ar = Adup + (ng + 32 * i) * ADP + 8 * kg;
            *reinterpret_cast<ulonglong2*>(ar)     = s01;
            *reinterpret_cast<ulonglong2*>(ar + 4) = s23;
        }
        __syncthreads();

        // ---- Stage B: V += A^T @ R, packed across c pairs. 32 rows per quarter.
        const int nbase = q * 32;
        #pragma unroll 4
        for (int nn = 0; nn < 32; ++nn) {
            const int n = nbase + nn;
            ulonglong2 a01 = *reinterpret_cast<const ulonglong2*>(Adup + n * ADP + 8 * kg2);
            ulonglong2 a23 = *reinterpret_cast<const ulonglong2*>(Adup + n * ADP + 8 * kg2 + 4);
            ulonglong2 r01 = *reinterpret_cast<const ulonglong2*>(Rrow + n * RP + 8 * cg);
            ulonglong2 r23 = *reinterpret_cast<const ulonglong2*>(Rrow + n * RP + 8 * cg + 4);
            FMA2(accB[0][0], a01.x, r01.x, accB[0][0]);
            FMA2(accB[0][1], a01.x, r01.y, accB[0][1]);
            FMA2(accB[0][2], a01.x, r23.x, accB[0][2]);
            FMA2(accB[0][3], a01.x, r23.y, accB[0][3]);
            FMA2(accB[1][0], a01.y, r01.x, accB[1][0]);
            FMA2(accB[1][1], a01.y, r01.y, accB[1][1]);
            FMA2(accB[1][2], a01.y, r23.x, accB[1][2]);
            FMA2(accB[1][3], a01.y, r23.y, accB[1][3]);
            FMA2(accB[2][0], a23.x, r01.x, accB[2][0]);
            FMA2(accB[2][1], a23.x, r01.y, accB[2][1]);
            FMA2(accB[2][2], a23.x, r23.x, accB[2][2]);
            FMA2(accB[2][3], a23.x, r23.y, accB[2][3]);
            FMA2(accB[3][0], a23.y, r01.x, accB[3][0]);
            FMA2(accB[3][1], a23.y, r01.y, accB[3][1]);
            FMA2(accB[3][2], a23.y, r23.x, accB[3][2]);
            FMA2(accB[3][3], a23.y, r23.y, accB[3][3]);
            ADD2(asum2[0], asum2[0], a01.x);
            ADD2(asum2[1], asum2[1], a01.y);
            ADD2(asum2[2], asum2[2], a23.x);
            ADD2(asum2[3], asum2[3], a23.y);
        }
    }

    // ---- Epilogue: fold -asum*centroid, reduce into out
    float* outm = out + (size_t)m * Kk * Cc;
    #pragma unroll
    for (int j = 0; j < 4; j++) {
        const int k = 4 * kg2 + j;
        float as, dummy;
        UNPK2(as, dummy, asum2[j]);
        const float* ck = cent + k * Cc + 8 * cg;
        float* o = outm + k * Cc + 8 * cg;
        #pragma unroll
        for (int p = 0; p < 4; p++) {
            float vlo, vhi;
            UNPK2(vlo, vhi, accB[j][p]);
            atomicAdd(o + 2 * p,     vlo - as * ck[2 * p]);
            atomicAdd(o + 2 * p + 1, vhi - as * ck[2 * p + 1]);
        }
    }
}

extern "C" void kernel_launch(void* const* d_in, const int* in_sizes, int n_in,
                              void* d_out, int out_size) {
    const float* R    = (const float*)d_in[0];
    const float* W    = (const float*)d_in[1];
    const float* b    = (const float*)d_in[2];
    const float* cent = (const float*)d_in[3];
    float* out = (float*)d_out;

    cudaFuncSetAttribute(nv_main, cudaFuncAttributeMaxDynamicSharedMemorySize, SMEM_BYTES);

    int n4 = out_size / 4;   // 131072 float4s
    nv_zero<<<(n4 + 255) / 256, 256>>>((float4*)out, n4);
    nv_main<<<BT * SPLIT, 256, SMEM_BYTES>>>(R, W, b, cent, out);
}

// round 3
// speedup vs baseline: 1.5981x; 1.5981x over previous
#include <cuda_runtime.h>
#include <cstdint>

// NetVLAD fused pool via 3xTF32 mma.sync (m16n8k8), sm_103a.
// One CTA per m (grid 256). Per 128-row tile:
//   Stage A: logits[n][k] = R[n][c]*W[k][c] + b  (tensor, 3-pass tf32)
//   softmax in fragments -> A'[k][n] smem (transposed)
//   Stage B: V[k][c] += A'[k][n]*R[n][c]         (tensor, 3-pass tf32)
// Epilogue: out[m][k][c] = V - asum[k]*cent[k][c]. No atomics, full overwrite.

#define MMA_TF32(d0,d1,d2,d3, a0,a1,a2,a3, b0,b1) \
  asm volatile("mma.sync.aligned.m16n8k8.row.col.f32.tf32.tf32.f32 " \
      "{%0,%1,%2,%3},{%4,%5,%6,%7},{%8,%9},{%0,%1,%2,%3};" \
      : "+f"(d0),"+f"(d1),"+f"(d2),"+f"(d3) \
      : "r"(a0),"r"(a1),"r"(a2),"r"(a3),"r"(b0),"r"(b1))

__device__ __forceinline__ uint32_t f2tf(float x){
    uint32_t r; asm("cvt.rna.tf32.f32 %0, %1;" : "=r"(r) : "f"(x)); return r;
}
__device__ __forceinline__ void split_tf(float x, uint32_t& h, uint32_t& l){
    h = f2tf(x);
    l = f2tf(x - __uint_as_float(h));
}

namespace {
constexpr int Nn = 2048, Cc = 64, Kk = 32;
constexpr int NT = 128, TILES = 16;
constexpr int RP = 68;    // Rs pitch (floats): stage-A frag loads conflict-free
constexpr int WP = 68;    // W pitch
constexpr int AP = 132;   // A' pitch
constexpr int OFF_RS = 0;                  // 128*68 floats
constexpr int OFF_WH = OFF_RS + NT * RP;   // 32*68
constexpr int OFF_WL = OFF_WH + Kk * WP;
constexpr int OFF_AP = OFF_WL + Kk * WP;   // 32*132
constexpr int OFF_AS = OFF_AP + Kk * AP;   // 32
constexpr int SMEM_BYTES = (OFF_AS + 32) * 4;  // ~69.5 KB
}

__global__ __launch_bounds__(256) void nv_tc(
    const float* __restrict__ R, const float* __restrict__ W,
    const float* __restrict__ bvec, const float* __restrict__ cent,
    float* __restrict__ out)
{
    extern __shared__ float sm[];
    float*    Rs      = sm + OFF_RS;
    uint32_t* Wh      = (uint32_t*)(sm + OFF_WH);
    uint32_t* Wl      = (uint32_t*)(sm + OFF_WL);
    float*    Apm     = sm + OFF_AP;
    float*    asum_sm = sm + OFF_AS;

    const int t    = threadIdx.x;
    const int m    = blockIdx.x;
    const int w    = t >> 5;
    const int lane = t & 31;
    const int g    = lane >> 2;   // groupID 0..7
    const int q    = lane & 3;    // threadID-in-group 0..3

    if (t < 32) asum_sm[t] = 0.f;

    // W (K=32, C=64) -> tf32 hi/lo in smem
    #pragma unroll
    for (int i = 0; i < 8; i++) {
        int idx = i * 256 + t;            // k*64 + c
        int k = idx >> 6, c = idx & 63;
        uint32_t h, l; split_tf(W[idx], h, l);
        Wh[k * WP + c] = h;
        Wl[k * WP + c] = l;
    }

    // bias for stage-A D init: cols k = 8*nb + 2*q + {0,1}
    float bias[4][2];
    #pragma unroll
    for (int nb = 0; nb < 4; nb++) {
        bias[nb][0] = bvec[8 * nb + 2 * q];
        bias[nb][1] = bvec[8 * nb + 2 * q + 1];
    }

    const int kb  = w & 1;          // stage-B k-block (rows 16*kb..)
    const int cb0 = (w >> 1) * 16;  // stage-B c-block base

    float vA[2][4];                 // stage-B accumulators (persist across tiles)
    float asl[4][2];                // asum partials: k = 8*nb + 2*q + j
    #pragma unroll
    for (int cb = 0; cb < 2; cb++)
        #pragma unroll
        for (int r = 0; r < 4; r++) vA[cb][r] = 0.f;
    #pragma unroll
    for (int nb = 0; nb < 4; nb++) { asl[nb][0] = 0.f; asl[nb][1] = 0.f; }

    const float* Rbase = R + (size_t)m * Nn * Cc;

    for (int tile = 0; tile < TILES; ++tile) {
        __syncthreads();   // previous stage B done with Rs/Apm

        // ---- load R tile (128x64), coalesced float4, natural layout
        const float4* Rg = (const float4*)(Rbase + (size_t)tile * NT * Cc);
        #pragma unroll
        for (int i = 0; i < 8; i++) {
            int idx = i * 256 + t;
            float4 v = Rg[idx];
            *(float4*)(Rs + (idx >> 4) * RP + (idx & 15) * 4) = v;
        }
        __syncthreads();

        // ---- Stage A: warp w owns rows 16w..16w+15; D[n][k], k-blocks nb
        float dA[4][4];
        #pragma unroll
        for (int nb = 0; nb < 4; nb++) {
            dA[nb][0] = bias[nb][0]; dA[nb][1] = bias[nb][1];
            dA[nb][2] = bias[nb][0]; dA[nb][3] = bias[nb][1];
        }
        const int rb = 16 * w;
        #pragma unroll 4
        for (int c0 = 0; c0 < 64; c0 += 8) {
            uint32_t ah[4], al[4];
            split_tf(Rs[(rb + g)     * RP + c0 + q],     ah[0], al[0]);
            split_tf(Rs[(rb + g + 8) * RP + c0 + q],     ah[1], al[1]);
            split_tf(Rs[(rb + g)     * RP + c0 + q + 4], ah[2], al[2]);
            split_tf(Rs[(rb + g + 8) * RP + c0 + q + 4], ah[3], al[3]);
            #pragma unroll
            for (int nb = 0; nb < 4; nb++) {
                const int kr = (8 * nb + g) * WP + c0;
                uint32_t bh0 = Wh[kr + q], bh1 = Wh[kr + q + 4];
                uint32_t bl0 = Wl[kr + q], bl1 = Wl[kr + q + 4];
                MMA_TF32(dA[nb][0],dA[nb][1],dA[nb][2],dA[nb][3],
                         ah[0],ah[1],ah[2],ah[3], bh0,bh1);
                MMA_TF32(dA[nb][0],dA[nb][1],dA[nb][2],dA[nb][3],
                         ah[0],ah[1],ah[2],ah[3], bl0,bl1);
                MMA_TF32(dA[nb][0],dA[nb][1],dA[nb][2],dA[nb][3],
                         al[0],al[1],al[2],al[3], bh0,bh1);
            }
        }

        // ---- softmax: thread holds rows rb+g (d0,d1) and rb+g+8 (d2,d3), 8 cols each
        float mx0 = -1e30f, mx1 = -1e30f;
        #pragma unroll
        for (int nb = 0; nb < 4; nb++) {
            mx0 = fmaxf(mx0, fmaxf(dA[nb][0], dA[nb][1]));
            mx1 = fmaxf(mx1, fmaxf(dA[nb][2], dA[nb][3]));
        }
        mx0 = fmaxf(mx0, __shfl_xor_sync(0xffffffffu, mx0, 1));
        mx0 = fmaxf(mx0, __shfl_xor_sync(0xffffffffu, mx0, 2));
        mx1 = fmaxf(mx1, __shfl_xor_sync(0xffffffffu, mx1, 1));
        mx1 = fmaxf(mx1, __shfl_xor_sync(0xffffffffu, mx1, 2));
        float s0 = 0.f, s1 = 0.f;
        #pragma unroll
        for (int nb = 0; nb < 4; nb++) {
            dA[nb][0] = __expf(dA[nb][0] - mx0);
            dA[nb][1] = __expf(dA[nb][1] - mx0);
            dA[nb][2] = __expf(dA[nb][2] - mx1);
            dA[nb][3] = __expf(dA[nb][3] - mx1);
            s0 += dA[nb][0] + dA[nb][1];
            s1 += dA[nb][2] + dA[nb][3];
        }
        s0 += __shfl_xor_sync(0xffffffffu, s0, 1);
        s0 += __shfl_xor_sync(0xffffffffu, s0, 2);
        s1 += __shfl_xor_sync(0xffffffffu, s1, 1);
        s1 += __shfl_xor_sync(0xffffffffu, s1, 2);
        const float inv0 = __fdividef(1.f, s0);
        const float inv1 = __fdividef(1.f, s1);
        #pragma unroll
        for (int nb = 0; nb < 4; nb++) {
            #pragma unroll
            for (int j = 0; j < 2; j++) {
                const int k = 8 * nb + 2 * q + j;
                float p0 = dA[nb][j]     * inv0;
                float p1 = dA[nb][j + 2] * inv1;
                Apm[k * AP + rb + g]     = p0;
                Apm[k * AP + rb + g + 8] = p1;
                asl[nb][j] += p0 + p1;
            }
        }
        __syncthreads();   // A' visible

        // ---- Stage B: warp w -> k-block kb, c-blocks {cb0, cb0+8}
        #pragma unroll 4
        for (int ks = 0; ks < 16; ks++) {
            const int n0 = 8 * ks;
            uint32_t ph[4], pl[4];
            split_tf(Apm[(16 * kb + g)     * AP + n0 + q],     ph[0], pl[0]);
            split_tf(Apm[(16 * kb + g + 8) * AP + n0 + q],     ph[1], pl[1]);
            split_tf(Apm[(16 * kb + g)     * AP + n0 + q + 4], ph[2], pl[2]);
            split_tf(Apm[(16 * kb + g + 8) * AP + n0 + q + 4], ph[3], pl[3]);
            #pragma unroll
            for (int cb = 0; cb < 2; cb++) {
                const int c0 = cb0 + 8 * cb;
                uint32_t rh0, rl0, rh1, rl1;
                split_tf(Rs[(n0 + q)     * RP + c0 + g], rh0, rl0);
                split_tf(Rs[(n0 + q + 4) * RP + c0 + g], rh1, rl1);
                MMA_TF32(vA[cb][0],vA[cb][1],vA[cb][2],vA[cb][3],
                         ph[0],ph[1],ph[2],ph[3], rh0,rh1);
                MMA_TF32(vA[cb][0],vA[cb][1],vA[cb][2],vA[cb][3],
                         ph[0],ph[1],ph[2],ph[3], rl0,rl1);
                MMA_TF32(vA[cb][0],vA[cb][1],vA[cb][2],vA[cb][3],
                         pl[0],pl[1],pl[2],pl[3], rh0,rh1);
            }
        }
    }

    // ---- asum: reduce over g within warp, atomic into smem
    #pragma unroll
    for (int nb = 0; nb < 4; nb++) {
        #pragma unroll
        for (int j = 0; j < 2; j++) {
            float v = asl[nb][j];
            v += __shfl_xor_sync(0xffffffffu, v, 4);
            v += __shfl_xor_sync(0xffffffffu, v, 8);
            v += __shfl_xor_sync(0xffffffffu, v, 16);
            if (g == 0) atomicAdd(&asum_sm[8 * nb + 2 * q + j], v);
        }
    }
    __syncthreads();

    // ---- epilogue: out[m][k][c] = V - asum[k]*cent[k][c]
    float* outm = out + (size_t)m * Kk * Cc;
    const int k0 = 16 * kb + g, k1 = k0 + 8;
    const float as0 = asum_sm[k0], as1 = asum_sm[k1];
    #pragma unroll
    for (int cb = 0; cb < 2; cb++) {
        const int c = cb0 + 8 * cb + 2 * q;
        const float2 c0v = *(const float2*)(cent + k0 * 64 + c);
        const float2 c1v = *(const float2*)(cent + k1 * 64 + c);
        float2 o0 = make_float2(vA[cb][0] - as0 * c0v.x, vA[cb][1] - as0 * c0v.y);
        float2 o1 = make_float2(vA[cb][2] - as1 * c1v.x, vA[cb][3] - as1 * c1v.y);
        *(float2*)(outm + k0 * 64 + c) = o0;
        *(float2*)(outm + k1 * 64 + c) = o1;
    }
}

extern "C" void kernel_launch(void* const* d_in, const int* in_sizes, int n_in,
                              void* d_out, int out_size) {
    const float* R    = (const float*)d_in[0];
    const float* W    = (const float*)d_in[1];
    const float* b    = (const float*)d_in[2];
    const float* cent = (const float*)d_in[3];
    float* out = (float*)d_out;

    cudaFuncSetAttribute(nv_tc, cudaFuncAttributeMaxDynamicSharedMemorySize, SMEM_BYTES);
    nv_tc<<<256, 256, SMEM_BYTES>>>(R, W, b, cent, out);
}

// round 5
// speedup vs baseline: 2.0504x; 1.2830x over previous
#include <cuda_runtime.h>
#include <cstdint>

// NetVLAD fused pool via 3xTF32 mma.sync (m16n8k8), sm_103a. Round 5.
// Grid = 1024 CTAs = (m, s in 0..3); rows [s*512, s*512+512), 4 tiles of 128.
// R and W presplit to tf32 hi/lo in smem (mask trick); A' stored fp32,
// split in-register in stage B. Smem 108KB -> 2 CTAs/SM.

#define MMA_TF32(d0,d1,d2,d3, a0,a1,a2,a3, b0,b1) \
  asm volatile("mma.sync.aligned.m16n8k8.row.col.f32.tf32.tf32.f32 " \
      "{%0,%1,%2,%3},{%4,%5,%6,%7},{%8,%9},{%0,%1,%2,%3};" \
      : "+f"(d0),"+f"(d1),"+f"(d2),"+f"(d3) \
      : "r"(a0),"r"(a1),"r"(a2),"r"(a3),"r"(b0),"r"(b1))

__device__ __forceinline__ void splitm(float x, uint32_t& h, uint32_t& l) {
    h = __float_as_uint(x) & 0xFFFFE000u;
    float lf = x - __uint_as_float(h);
    l = __float_as_uint(lf) & 0xFFFFE000u;
}

namespace {
constexpr int Nn = 2048, Cc = 64, Kk = 32;
constexpr int SPLIT = 4, NT = 128;
constexpr int TILES = (Nn / SPLIT) / NT;        // 4
constexpr int RP  = 72;    // R hi/lo pitch: stage-B frag loads conflict-free
constexpr int WPp = 68;    // W pitch (>=64 + pad): stage-A frag loads conflict-free
constexpr int APp = 132;   // A' pitch (>=128 + pad): frag loads + STS conflict-free
constexpr int OFF_RH = 0;
constexpr int OFF_RL = OFF_RH + NT * RP;        // 9216
constexpr int OFF_WH = OFF_RL + NT * RP;        // 18432
constexpr int OFF_WL = OFF_WH + Kk * WPp;       // 20608
constexpr int OFF_AP = OFF_WL + Kk * WPp;       // 22784
constexpr int OFF_AS = OFF_AP + Kk * APp;       // 27008 (asum[32])
constexpr int SMEM_BYTES = (OFF_AS + 32) * 4;   // 108,160 B -> 2 CTAs/SM
}

__global__ void nv_zero(float4* __restrict__ out, int n4) {
    int i = blockIdx.x * blockDim.x + threadIdx.x;
    if (i < n4) out[i] = make_float4(0.f, 0.f, 0.f, 0.f);
}

__global__ __launch_bounds__(256, 2) void nv_tc(
    const float* __restrict__ R, const float* __restrict__ W,
    const float* __restrict__ bvec, const float* __restrict__ cent,
    float* __restrict__ out)
{
    extern __shared__ float sm[];
    uint32_t* Rh = (uint32_t*)(sm + OFF_RH);
    uint32_t* Rl = (uint32_t*)(sm + OFF_RL);
    uint32_t* Wh = (uint32_t*)(sm + OFF_WH);
    uint32_t* Wl = (uint32_t*)(sm + OFF_WL);
    float*    Ap = sm + OFF_AP;
    float* asum_sm = sm + OFF_AS;

    const int t    = threadIdx.x;
    const int m    = blockIdx.x >> 2;
    const int s    = blockIdx.x & 3;
    const int w    = t >> 5;
    const int lane = t & 31;
    const int g    = lane >> 2;   // 0..7
    const int q    = lane & 3;    // 0..3

    if (t < 32) asum_sm[t] = 0.f;

    // W (K=32, C=64) -> tf32 hi/lo in smem (split once per CTA)
    #pragma unroll
    for (int i = 0; i < 8; i++) {
        int idx = i * 256 + t;            // k*64 + c
        int k = idx >> 6, c = idx & 63;
        uint32_t h, l; splitm(W[idx], h, l);
        Wh[k * WPp + c] = h;
        Wl[k * WPp + c] = l;
    }

    float bias[4][2];
    #pragma unroll
    for (int nb = 0; nb < 4; nb++) {
        bias[nb][0] = bvec[8 * nb + 2 * q];
        bias[nb][1] = bvec[8 * nb + 2 * q + 1];
    }

    const int kb  = w & 1;           // stage-B k-block
    const int cb0 = (w >> 1) * 16;   // stage-B c base

    float vA[2][4];
    float asl[4][2];
    #pragma unroll
    for (int cb = 0; cb < 2; cb++)
        #pragma unroll
        for (int r = 0; r < 4; r++) vA[cb][r] = 0.f;
    #pragma unroll
    for (int nb = 0; nb < 4; nb++) { asl[nb][0] = 0.f; asl[nb][1] = 0.f; }

    const float* Rbase = R + ((size_t)m * Nn + (size_t)s * (Nn / SPLIT)) * Cc;

    // prefetch tile 0
    float4 pf[8];
    {
        const float4* Rg = (const float4*)Rbase;
        #pragma unroll
        for (int i = 0; i < 8; i++) pf[i] = Rg[i * 256 + t];
    }

    for (int tile = 0; tile < TILES; ++tile) {
        if (tile > 0) __syncthreads();   // stage B done reading Rh/Rl/Ap

        // ---- split prefetched tile into Rh/Rl
        #pragma unroll
        for (int i = 0; i < 8; i++) {
            int idx = i * 256 + t;
            int addr = (idx >> 4) * RP + (idx & 15) * 4;   // RP mult of 4 -> 16B aligned
            uint4 h4, l4;
            splitm(pf[i].x, h4.x, l4.x);
            splitm(pf[i].y, h4.y, l4.y);
            splitm(pf[i].z, h4.z, l4.z);
            splitm(pf[i].w, h4.w, l4.w);
            *(uint4*)(Rh + addr) = h4;
            *(uint4*)(Rl + addr) = l4;
        }
        __syncthreads();

        // ---- prefetch next tile (hidden under stage A/B compute)
        if (tile + 1 < TILES) {
            const float4* Rg = (const float4*)(Rbase + (size_t)(tile + 1) * NT * Cc);
            #pragma unroll
            for (int i = 0; i < 8; i++) pf[i] = Rg[i * 256 + t];
        }

        // ---- Stage A: warp w owns rows 16w..16w+15
        float dA[4][4];
        #pragma unroll
        for (int nb = 0; nb < 4; nb++) {
            dA[nb][0] = bias[nb][0]; dA[nb][1] = bias[nb][1];
            dA[nb][2] = bias[nb][0]; dA[nb][3] = bias[nb][1];
        }
        const int rb = 16 * w;
        #pragma unroll
        for (int c0 = 0; c0 < 64; c0 += 8) {
            const int r0 = (rb + g) * RP + c0;
            const int r1 = (rb + g + 8) * RP + c0;
            uint32_t ah[4], al[4];
            ah[0] = Rh[r0 + q];     al[0] = Rl[r0 + q];
            ah[1] = Rh[r1 + q];     al[1] = Rl[r1 + q];
            ah[2] = Rh[r0 + q + 4]; al[2] = Rl[r0 + q + 4];
            ah[3] = Rh[r1 + q + 4]; al[3] = Rl[r1 + q + 4];
            #pragma unroll
            for (int nb = 0; nb < 4; nb++) {
                const int kr = (8 * nb + g) * WPp + c0;
                uint32_t bh0 = Wh[kr + q], bh1 = Wh[kr + q + 4];
                uint32_t bl0 = Wl[kr + q], bl1 = Wl[kr + q + 4];
                MMA_TF32(dA[nb][0],dA[nb][1],dA[nb][2],dA[nb][3],
                         ah[0],ah[1],ah[2],ah[3], bh0,bh1);
                MMA_TF32(dA[nb][0],dA[nb][1],dA[nb][2],dA[nb][3],
                         ah[0],ah[1],ah[2],ah[3], bl0,bl1);
                MMA_TF32(dA[nb][0],dA[nb][1],dA[nb][2],dA[nb][3],
                         al[0],al[1],al[2],al[3], bh0,bh1);
            }
        }

        // ---- softmax over k (thread holds rows rb+g and rb+g+8)
        float mx0 = -1e30f, mx1 = -1e30f;
        #pragma unroll
        for (int nb = 0; nb < 4; nb++) {
            mx0 = fmaxf(mx0, fmaxf(dA[nb][0], dA[nb][1]));
            mx1 = fmaxf(mx1, fmaxf(dA[nb][2], dA[nb][3]));
        }
        mx0 = fmaxf(mx0, __shfl_xor_sync(0xffffffffu, mx0, 1));
        mx0 = fmaxf(mx0, __shfl_xor_sync(0xffffffffu, mx0, 2));
        mx1 = fmaxf(mx1, __shfl_xor_sync(0xffffffffu, mx1, 1));
        mx1 = fmaxf(mx1, __shfl_xor_sync(0xffffffffu, mx1, 2));
        float s0 = 0.f, s1 = 0.f;
        #pragma unroll
        for (int nb = 0; nb < 4; nb++) {
            dA[nb][0] = __expf(dA[nb][0] - mx0);
            dA[nb][1] = __expf(dA[nb][1] - mx0);
            dA[nb][2] = __expf(dA[nb][2] - mx1);
            dA[nb][3] = __expf(dA[nb][3] - mx1);
            s0 += dA[nb][0] + dA[nb][1];
            s1 += dA[nb][2] + dA[nb][3];
        }
        s0 += __shfl_xor_sync(0xffffffffu, s0, 1);
        s0 += __shfl_xor_sync(0xffffffffu, s0, 2);
        s1 += __shfl_xor_sync(0xffffffffu, s1, 1);
        s1 += __shfl_xor_sync(0xffffffffu, s1, 2);
        const float inv0 = __fdividef(1.f, s0);
        const float inv1 = __fdividef(1.f, s1);
        #pragma unroll
        for (int nb = 0; nb < 4; nb++) {
            #pragma unroll
            for (int j = 0; j < 2; j++) {
                const int k = 8 * nb + 2 * q + j;
                float p0 = dA[nb][j]     * inv0;
                float p1 = dA[nb][j + 2] * inv1;
                Ap[k * APp + rb + g]     = p0;
                Ap[k * APp + rb + g + 8] = p1;
                asl[nb][j] += p0 + p1;
            }
        }
        __syncthreads();   // A' visible

        // ---- Stage B: V[k][c] += A'[k][n] * R[n][c] (split A in-register)
        #pragma unroll 4
        for (int ks = 0; ks < 16; ks++) {
            const int n0 = 8 * ks;
            const int a0 = (16 * kb + g) * APp + n0;
            const int a1 = (16 * kb + g + 8) * APp + n0;
            uint32_t ph[4], pl[4];
            splitm(Ap[a0 + q],     ph[0], pl[0]);
            splitm(Ap[a1 + q],     ph[1], pl[1]);
            splitm(Ap[a0 + q + 4], ph[2], pl[2]);
            splitm(Ap[a1 + q + 4], ph[3], pl[3]);
            #pragma unroll
            for (int cb = 0; cb < 2; cb++) {
                const int c0 = cb0 + 8 * cb;
                const int b0i = (n0 + q) * RP + c0 + g;
                const int b1i = (n0 + q + 4) * RP + c0 + g;
                uint32_t rh0 = Rh[b0i], rl0 = Rl[b0i];
                uint32_t rh1 = Rh[b1i], rl1 = Rl[b1i];
                MMA_TF32(vA[cb][0],vA[cb][1],vA[cb][2],vA[cb][3],
                         ph[0],ph[1],ph[2],ph[3], rh0,rh1);
                MMA_TF32(vA[cb][0],vA[cb][1],vA[cb][2],vA[cb][3],
                         ph[0],ph[1],ph[2],ph[3], rl0,rl1);
                MMA_TF32(vA[cb][0],vA[cb][1],vA[cb][2],vA[cb][3],
                         pl[0],pl[1],pl[2],pl[3], rh0,rh1);
            }
        }
    }

    // ---- asum: reduce across g within warp
    #pragma unroll
    for (int nb = 0; nb < 4; nb++) {
        #pragma unroll
        for (int j = 0; j < 2; j++) {
            float v = asl[nb][j];
            v += __shfl_xor_sync(0xffffffffu, v, 4);
            v += __shfl_xor_sync(0xffffffffu, v, 8);
            v += __shfl_xor_sync(0xffffffffu, v, 16);
            if (g == 0) atomicAdd(&asum_sm[8 * nb + 2 * q + j], v);
        }
    }
    __syncthreads();

    // ---- epilogue: atomicAdd(out, V - asum*cent)
    float* outm = out + (size_t)m * Kk * Cc;
    const int k0 = 16 * kb + g, k1 = k0 + 8;
    const float as0 = asum_sm[k0], as1 = asum_sm[k1];
    #pragma unroll
    for (int cb = 0; cb < 2; cb++) {
        const int c = cb0 + 8 * cb + 2 * q;
        const float2 c0v = *(const float2*)(cent + k0 * 64 + c);
        const float2 c1v = *(const float2*)(cent + k1 * 64 + c);
        atomicAdd(outm + k0 * 64 + c,     vA[cb][0] - as0 * c0v.x);
        atomicAdd(outm + k0 * 64 + c + 1, vA[cb][1] - as0 * c0v.y);
        atomicAdd(outm + k1 * 64 + c,     vA[cb][2] - as1 * c1v.x);
        atomicAdd(outm + k1 * 64 + c + 1, vA[cb][3] - as1 * c1v.y);
    }
}

extern "C" void kernel_launch(void* const* d_in, const int* in_sizes, int n_in,
                              void* d_out, int out_size) {
    const float* R    = (const float*)d_in[0];
    const float* W    = (const float*)d_in[1];
    const float* b    = (const float*)d_in[2];
    const float* cent = (const float*)d_in[3];
    float* out = (float*)d_out;

    cudaFuncSetAttribute(nv_tc, cudaFuncAttributeMaxDynamicSharedMemorySize, SMEM_BYTES);
    int n4 = out_size / 4;
    nv_zero<<<(n4 + 255) / 256, 256>>>((float4*)out, n4);
    nv_tc<<<256 * SPLIT, 256, SMEM_BYTES>>>(R, W, b, cent, out);
}

// round 6
// speedup vs baseline: 2.0949x; 1.0217x over previous
#include <cuda_runtime.h>
#include <cstdint>

// NetVLAD fused pool via 3xTF32 mma.sync (m16n8k8), sm_103a. Round 5.
// Grid = 1024 CTAs = (m, s in 0..3); rows [s*512, s*512+512), 4 tiles of 128.
// R and W presplit to tf32 hi/lo in smem (mask trick); A' stored fp32,
// split in-register in stage B. Smem 108KB -> 2 CTAs/SM.

#define MMA_TF32(d0,d1,d2,d3, a0,a1,a2,a3, b0,b1) \
  asm volatile("mma.sync.aligned.m16n8k8.row.col.f32.tf32.tf32.f32 " \
      "{%0,%1,%2,%3},{%4,%5,%6,%7},{%8,%9},{%0,%1,%2,%3};" \
      : "+f"(d0),"+f"(d1),"+f"(d2),"+f"(d3) \
      : "r"(a0),"r"(a1),"r"(a2),"r"(a3),"r"(b0),"r"(b1))

__device__ __forceinline__ void splitm(float x, uint32_t& h, uint32_t& l) {
    h = __float_as_uint(x) & 0xFFFFE000u;
    float lf = x - __uint_as_float(h);
    l = __float_as_uint(lf) & 0xFFFFE000u;
}

namespace {
constexpr int Nn = 2048, Cc = 64, Kk = 32;
constexpr int SPLIT = 4, NT = 128;
constexpr int TILES = (Nn / SPLIT) / NT;        // 4
constexpr int RP  = 72;    // R hi/lo pitch: stage-B frag loads conflict-free
constexpr int WPp = 68;    // W pitch (>=64 + pad): stage-A frag loads conflict-free
constexpr int APp = 132;   // A' pitch (>=128 + pad): frag loads + STS conflict-free
constexpr int OFF_RH = 0;
constexpr int OFF_RL = OFF_RH + NT * RP;        // 9216
constexpr int OFF_WH = OFF_RL + NT * RP;        // 18432
constexpr int OFF_WL = OFF_WH + Kk * WPp;       // 20608
constexpr int OFF_AP = OFF_WL + Kk * WPp;       // 22784
constexpr int OFF_AS = OFF_AP + Kk * APp;       // 27008 (asum[32])
constexpr int SMEM_BYTES = (OFF_AS + 32) * 4;   // 108,160 B -> 2 CTAs/SM
}

__global__ void nv_zero(float4* __restrict__ out, int n4) {
    int i = blockIdx.x * blockDim.x + threadIdx.x;
    if (i < n4) out[i] = make_float4(0.f, 0.f, 0.f, 0.f);
}

__global__ __launch_bounds__(256, 2) void nv_tc(
    const float* __restrict__ R, const float* __restrict__ W,
    const float* __restrict__ bvec, const float* __restrict__ cent,
    float* __restrict__ out)
{
    extern __shared__ float sm[];
    uint32_t* Rh = (uint32_t*)(sm + OFF_RH);
    uint32_t* Rl = (uint32_t*)(sm + OFF_RL);
    uint32_t* Wh = (uint32_t*)(sm + OFF_WH);
    uint32_t* Wl = (uint32_t*)(sm + OFF_WL);
    float*    Ap = sm + OFF_AP;
    float* asum_sm = sm + OFF_AS;

    const int t    = threadIdx.x;
    const int m    = blockIdx.x >> 2;
    const int s    = blockIdx.x & 3;
    const int w    = t >> 5;
    const int lane = t & 31;
    const int g    = lane >> 2;   // 0..7
    const int q    = lane & 3;    // 0..3

    if (t < 32) asum_sm[t] = 0.f;

    // W (K=32, C=64) -> tf32 hi/lo in smem (split once per CTA)
    #pragma unroll
    for (int i = 0; i < 8; i++) {
        int idx = i * 256 + t;            // k*64 + c
        int k = idx >> 6, c = idx & 63;
        uint32_t h, l; splitm(W[idx], h, l);
        Wh[k * WPp + c] = h;
        Wl[k * WPp + c] = l;
    }

    float bias[4][2];
    #pragma unroll
    for (int nb = 0; nb < 4; nb++) {
        bias[nb][0] = bvec[8 * nb + 2 * q];
        bias[nb][1] = bvec[8 * nb + 2 * q + 1];
    }

    const int kb  = w & 1;           // stage-B k-block
    const int cb0 = (w >> 1) * 16;   // stage-B c base

    float vA[2][4];
    float asl[4][2];
    #pragma unroll
    for (int cb = 0; cb < 2; cb++)
        #pragma unroll
        for (int r = 0; r < 4; r++) vA[cb][r] = 0.f;
    #pragma unroll
    for (int nb = 0; nb < 4; nb++) { asl[nb][0] = 0.f; asl[nb][1] = 0.f; }

    const float* Rbase = R + ((size_t)m * Nn + (size_t)s * (Nn / SPLIT)) * Cc;

    // prefetch tile 0
    float4 pf[8];
    {
        const float4* Rg = (const float4*)Rbase;
        #pragma unroll
        for (int i = 0; i < 8; i++) pf[i] = Rg[i * 256 + t];
    }

    for (int tile = 0; tile < TILES; ++tile) {
        if (tile > 0) __syncthreads();   // stage B done reading Rh/Rl/Ap

        // ---- split prefetched tile into Rh/Rl
        #pragma unroll
        for (int i = 0; i < 8; i++) {
            int idx = i * 256 + t;
            int addr = (idx >> 4) * RP + (idx & 15) * 4;   // RP mult of 4 -> 16B aligned
            uint4 h4, l4;
            splitm(pf[i].x, h4.x, l4.x);
            splitm(pf[i].y, h4.y, l4.y);
            splitm(pf[i].z, h4.z, l4.z);
            splitm(pf[i].w, h4.w, l4.w);
            *(uint4*)(Rh + addr) = h4;
            *(uint4*)(Rl + addr) = l4;
        }
        __syncthreads();

        // ---- prefetch next tile (hidden under stage A/B compute)
        if (tile + 1 < TILES) {
            const float4* Rg = (const float4*)(Rbase + (size_t)(tile + 1) * NT * Cc);
            #pragma unroll
            for (int i = 0; i < 8; i++) pf[i] = Rg[i * 256 + t];
        }

        // ---- Stage A: warp w owns rows 16w..16w+15
        float dA[4][4];
        #pragma unroll
        for (int nb = 0; nb < 4; nb++) {
            dA[nb][0] = bias[nb][0]; dA[nb][1] = bias[nb][1];
            dA[nb][2] = bias[nb][0]; dA[nb][3] = bias[nb][1];
        }
        const int rb = 16 * w;
        #pragma unroll
        for (int c0 = 0; c0 < 64; c0 += 8) {
            const int r0 = (rb + g) * RP + c0;
            const int r1 = (rb + g + 8) * RP + c0;
            uint32_t ah[4], al[4];
            ah[0] = Rh[r0 + q];     al[0] = Rl[r0 + q];
            ah[1] = Rh[r1 + q];     al[1] = Rl[r1 + q];
            ah[2] = Rh[r0 + q + 4]; al[2] = Rl[r0 + q + 4];
            ah[3] = Rh[r1 + q + 4]; al[3] = Rl[r1 + q + 4];
            #pragma unroll
            for (int nb = 0; nb < 4; nb++) {
                const int kr = (8 * nb + g) * WPp + c0;
                uint32_t bh0 = Wh[kr + q], bh1 = Wh[kr + q + 4];
                uint32_t bl0 = Wl[kr + q], bl1 = Wl[kr + q + 4];
                MMA_TF32(dA[nb][0],dA[nb][1],dA[nb][2],dA[nb][3],
                         ah[0],ah[1],ah[2],ah[3], bh0,bh1);
                MMA_TF32(dA[nb][0],dA[nb][1],dA[nb][2],dA[nb][3],
                         ah[0],ah[1],ah[2],ah[3], bl0,bl1);
                MMA_TF32(dA[nb][0],dA[nb][1],dA[nb][2],dA[nb][3],
                         al[0],al[1],al[2],al[3], bh0,bh1);
            }
        }

        // ---- softmax over k (thread holds rows rb+g and rb+g+8)
        float mx0 = -1e30f, mx1 = -1e30f;
        #pragma unroll
        for (int nb = 0; nb < 4; nb++) {
            mx0 = fmaxf(mx0, fmaxf(dA[nb][0], dA[nb][1]));
            mx1 = fmaxf(mx1, fmaxf(dA[nb][2], dA[nb][3]));
        }
        mx0 = fmaxf(mx0, __shfl_xor_sync(0xffffffffu, mx0, 1));
        mx0 = fmaxf(mx0, __shfl_xor_sync(0xffffffffu, mx0, 2));
        mx1 = fmaxf(mx1, __shfl_xor_sync(0xffffffffu, mx1, 1));
        mx1 = fmaxf(mx1, __shfl_xor_sync(0xffffffffu, mx1, 2));
        float s0 = 0.f, s1 = 0.f;
        #pragma unroll
        for (int nb = 0; nb < 4; nb++) {
            dA[nb][0] = __expf(dA[nb][0] - mx0);
            dA[nb][1] = __expf(dA[nb][1] - mx0);
            dA[nb][2] = __expf(dA[nb][2] - mx1);
            dA[nb][3] = __expf(dA[nb][3] - mx1);
            s0 += dA[nb][0] + dA[nb][1];
            s1 += dA[nb][2] + dA[nb][3];
        }
        s0 += __shfl_xor_sync(0xffffffffu, s0, 1);
        s0 += __shfl_xor_sync(0xffffffffu, s0, 2);
        s1 += __shfl_xor_sync(0xffffffffu, s1, 1);
        s1 += __shfl_xor_sync(0xffffffffu, s1, 2);
        const float inv0 = __fdividef(1.f, s0);
        const float inv1 = __fdividef(1.f, s1);
        #pragma unroll
        for (int nb = 0; nb < 4; nb++) {
            #pragma unroll
            for (int j = 0; j < 2; j++) {
                const int k = 8 * nb + 2 * q + j;
                float p0 = dA[nb][j]     * inv0;
                float p1 = dA[nb][j + 2] * inv1;
                Ap[k * APp + rb + g]     = p0;
                Ap[k * APp + rb + g + 8] = p1;
                asl[nb][j] += p0 + p1;
            }
        }
        __syncthreads();   // A' visible

        // ---- Stage B: V[k][c] += A'[k][n] * R[n][c] (split A in-register)
        #pragma unroll 4
        for (int ks = 0; ks < 16; ks++) {
            const int n0 = 8 * ks;
            const int a0 = (16 * kb + g) * APp + n0;
            const int a1 = (16 * kb + g + 8) * APp + n0;
            uint32_t ph[4], pl[4];
            splitm(Ap[a0 + q],     ph[0], pl[0]);
            splitm(Ap[a1 + q],     ph[1], pl[1]);
            splitm(Ap[a0 + q + 4], ph[2], pl[2]);
            splitm(Ap[a1 + q + 4], ph[3], pl[3]);
            #pragma unroll
            for (int cb = 0; cb < 2; cb++) {
                const int c0 = cb0 + 8 * cb;
                const int b0i = (n0 + q) * RP + c0 + g;
                const int b1i = (n0 + q + 4) * RP + c0 + g;
                uint32_t rh0 = Rh[b0i], rl0 = Rl[b0i];
                uint32_t rh1 = Rh[b1i], rl1 = Rl[b1i];
                MMA_TF32(vA[cb][0],vA[cb][1],vA[cb][2],vA[cb][3],
                         ph[0],ph[1],ph[2],ph[3], rh0,rh1);
                MMA_TF32(vA[cb][0],vA[cb][1],vA[cb][2],vA[cb][3],
                         ph[0],ph[1],ph[2],ph[3], rl0,rl1);
                MMA_TF32(vA[cb][0],vA[cb][1],vA[cb][2],vA[cb][3],
                         pl[0],pl[1],pl[2],pl[3], rh0,rh1);
            }
        }
    }

    // ---- asum: reduce across g within warp
    #pragma unroll
    for (int nb = 0; nb < 4; nb++) {
        #pragma unroll
        for (int j = 0; j < 2; j++) {
            float v = asl[nb][j];
            v += __shfl_xor_sync(0xffffffffu, v, 4);
            v += __shfl_xor_sync(0xffffffffu, v, 8);
            v += __shfl_xor_sync(0xffffffffu, v, 16);
            if (g == 0) atomicAdd(&asum_sm[8 * nb + 2 * q + j], v);
        }
    }
    __syncthreads();

    // ---- epilogue: atomicAdd(out, V - asum*cent)
    float* outm = out + (size_t)m * Kk * Cc;
    const int k0 = 16 * kb + g, k1 = k0 + 8;
    const float as0 = asum_sm[k0], as1 = asum_sm[k1];
    #pragma unroll
    for (int cb = 0; cb < 2; cb++) {
        const int c = cb0 + 8 * cb + 2 * q;
        const float2 c0v = *(const float2*)(cent + k0 * 64 + c);
        const float2 c1v = *(const float2*)(cent + k1 * 64 + c);
        atomicAdd(outm + k0 * 64 + c,     vA[cb][0] - as0 * c0v.x);
        atomicAdd(outm + k0 * 64 + c + 1, vA[cb][1] - as0 * c0v.y);
        atomicAdd(outm + k1 * 64 + c,     vA[cb][2] - as1 * c1v.x);
        atomicAdd(outm + k1 * 64 + c + 1, vA[cb][3] - as1 * c1v.y);
    }
}

extern "C" void kernel_launch(void* const* d_in, const int* in_sizes, int n_in,
                              void* d_out, int out_size) {
    const float* R    = (const float*)d_in[0];
    const float* W    = (const float*)d_in[1];
    const float* b    = (const float*)d_in[2];
    const float* cent = (const float*)d_in[3];
    float* out = (float*)d_out;

    cudaFuncSetAttribute(nv_tc, cudaFuncAttributeMaxDynamicSharedMemorySize, SMEM_BYTES);
    int n4 = out_size / 4;
    nv_zero<<<(n4 + 255) / 256, 256>>>((float4*)out, n4);
    nv_tc<<<256 * SPLIT, 256, SMEM_BYTES>>>(R, W, b, cent, out);
}

// round 7
// speedup vs baseline: 2.5969x; 1.2397x over previous
#include <cuda_runtime.h>
#include <cstdint>

// NetVLAD fused pool via 3-product BF16 mma.sync (m16n8k16), sm_103a. Round 7.
// Grid = 1024 CTAs = (m, s); 4 tiles of 128 rows. R stored twice in smem as
// bf16x2 hi/lo: Rc packed over c (stage A k-dim), Rn packed over n (stage B k-dim).
// A' packed over n via shfl. 3 products (hh, hl, lh) ~= fp32 accuracy.

#define MMA_BF16(d0,d1,d2,d3, a0,a1,a2,a3, b0,b1) \
  asm volatile("mma.sync.aligned.m16n8k16.row.col.f32.bf16.bf16.f32 " \
      "{%0,%1,%2,%3},{%4,%5,%6,%7},{%8,%9},{%0,%1,%2,%3};" \
      : "+f"(d0),"+f"(d1),"+f"(d2),"+f"(d3) \
      : "r"(a0),"r"(a1),"r"(a2),"r"(a3),"r"(b0),"r"(b1))

__device__ __forceinline__ void splitb(float x, uint32_t& h, uint32_t& l) {
    h = __float_as_uint(x) & 0xFFFF0000u;
    float lf = x - __uint_as_float(h);
    l = __float_as_uint(lf) & 0xFFFF0000u;
}
__device__ __forceinline__ uint32_t packb(uint32_t xh, uint32_t yh) {
    return (xh >> 16) | (yh & 0xFFFF0000u);   // x -> low half (even idx), y -> high
}

namespace {
constexpr int Nn = 2048, Cc = 64, Kk = 32;
constexpr int SPLIT = 4, NT = 128;
constexpr int TILES = (Nn / SPLIT) / NT;   // 4
constexpr int RCP = 36;   // Rc pitch (cpairs)
constexpr int RNP = 72;   // Rn pitch (c words)  -- 72 for CF 8q+g banks
constexpr int WCP = 36;   // Wc pitch (cpairs)
constexpr int AKP = 68;   // Ak pitch (npairs)
constexpr int O_RCH = 0;
constexpr int O_RCL = O_RCH + NT * RCP;          // 4608
constexpr int O_RNH = O_RCL + NT * RCP;          // 9216
constexpr int O_RNL = O_RNH + 64 * RNP;          // 13824
constexpr int O_WCH = O_RNL + 64 * RNP;          // 18432
constexpr int O_WCL = O_WCH + Kk * WCP;
constexpr int O_AKH = O_WCL + Kk * WCP;
constexpr int O_AKL = O_AKH + Kk * AKP;
constexpr int O_AS  = O_AKL + Kk * AKP;
constexpr int SMEM_BYTES = (O_AS + 32) * 4;      // ~100.5 KB -> 2 CTAs/SM
}

__global__ void nv_zero(float4* __restrict__ out, int n4) {
    int i = blockIdx.x * blockDim.x + threadIdx.x;
    if (i < n4) out[i] = make_float4(0.f, 0.f, 0.f, 0.f);
}

__global__ __launch_bounds__(256, 2) void nv_tc(
    const float* __restrict__ R, const float* __restrict__ W,
    const float* __restrict__ bvec, const float* __restrict__ cent,
    float* __restrict__ out)
{
    extern __shared__ float sm[];
    uint32_t* RCH = (uint32_t*)(sm + O_RCH);
    uint32_t* RCL = (uint32_t*)(sm + O_RCL);
    uint32_t* RNH = (uint32_t*)(sm + O_RNH);
    uint32_t* RNL = (uint32_t*)(sm + O_RNL);
    uint32_t* WCH = (uint32_t*)(sm + O_WCH);
    uint32_t* WCL = (uint32_t*)(sm + O_WCL);
    uint32_t* AKH = (uint32_t*)(sm + O_AKH);
    uint32_t* AKL = (uint32_t*)(sm + O_AKL);
    float* asum_sm = sm + O_AS;

    const int t    = threadIdx.x;
    const int m    = blockIdx.x >> 2;
    const int s    = blockIdx.x & 3;
    const int w    = t >> 5;
    const int lane = t & 31;
    const int g    = lane >> 2;
    const int q    = lane & 3;
    const bool evenlane = (lane & 4) == 0;   // g even

    if (t < 32) asum_sm[t] = 0.f;

    // W (K=32, C=64) -> bf16x2 hi/lo packed over c pairs
    #pragma unroll
    for (int i = 0; i < 4; i++) {
        int idx = i * 256 + t;              // pair index: k*32 + cp
        int k = idx >> 5, cp = idx & 31;
        float2 wv = ((const float2*)W)[idx];
        uint32_t xh, xl, yh, yl;
        splitb(wv.x, xh, xl); splitb(wv.y, yh, yl);
        WCH[k * WCP + cp] = packb(xh, yh);
        WCL[k * WCP + cp] = packb(xl, yl);
    }

    float bias[4][2];
    #pragma unroll
    for (int nb = 0; nb < 4; nb++) {
        bias[nb][0] = bvec[8 * nb + 2 * q];
        bias[nb][1] = bvec[8 * nb + 2 * q + 1];
    }

    const int kb  = w & 1;
    const int cb0 = (w >> 1) * 16;
    const int rb  = 16 * w;
    const int col4 = t & 15;     // loader: float4 column
    const int rp0  = t >> 4;     // loader: base rowpair

    float vA[2][4];
    float asl[4][2];
    #pragma unroll
    for (int cb = 0; cb < 2; cb++)
        #pragma unroll
        for (int r = 0; r < 4; r++) vA[cb][r] = 0.f;
    #pragma unroll
    for (int nb = 0; nb < 4; nb++) { asl[nb][0] = 0.f; asl[nb][1] = 0.f; }

    const float* Rbase = R + ((size_t)m * Nn + (size_t)s * (Nn / SPLIT)) * Cc;

    // prefetch tile 0: per j, rows 2rp and 2rp+1, float4 col4 (coalesced 512B/warp)
    float4 pfa[4], pfb[4];
    {
        const float4* Rg = (const float4*)Rbase;
        #pragma unroll
        for (int j = 0; j < 4; j++) {
            int rp = rp0 + 16 * j;
            pfa[j] = Rg[(2 * rp) * 16 + col4];
            pfb[j] = Rg[(2 * rp + 1) * 16 + col4];
        }
    }

    for (int tile = 0; tile < TILES; ++tile) {
        if (tile > 0) __syncthreads();   // prior stage A/B done with Rc/Rn/Ak

        // ---- split + dual-layout store (in-register, no shuffles)
        #pragma unroll
        for (int j = 0; j < 4; j++) {
            const int rp = rp0 + 16 * j;
            uint32_t ah[4], al[4], bh[4], bl[4];
            splitb(pfa[j].x, ah[0], al[0]); splitb(pfa[j].y, ah[1], al[1]);
            splitb(pfa[j].z, ah[2], al[2]); splitb(pfa[j].w, ah[3], al[3]);
            splitb(pfb[j].x, bh[0], bl[0]); splitb(pfb[j].y, bh[1], bl[1]);
            splitb(pfb[j].z, bh[2], bl[2]); splitb(pfb[j].w, bh[3], bl[3]);
            // Rc: rows 2rp, 2rp+1; cpairs 2*col4, 2*col4+1
            *(uint2*)(RCH + (2 * rp) * RCP + 2 * col4)     = make_uint2(packb(ah[0],ah[1]), packb(ah[2],ah[3]));
            *(uint2*)(RCL + (2 * rp) * RCP + 2 * col4)     = make_uint2(packb(al[0],al[1]), packb(al[2],al[3]));
            *(uint2*)(RCH + (2 * rp + 1) * RCP + 2 * col4) = make_uint2(packb(bh[0],bh[1]), packb(bh[2],bh[3]));
            *(uint2*)(RCL + (2 * rp + 1) * RCP + 2 * col4) = make_uint2(packb(bl[0],bl[1]), packb(bl[2],bl[3]));
            // Rn: npair rp, c = 4*col4..+3
            uint4 nh, nl;
            nh.x = packb(ah[0], bh[0]); nl.x = packb(al[0], bl[0]);
            nh.y = packb(ah[1], bh[1]); nl.y = packb(al[1], bl[1]);
            nh.z = packb(ah[2], bh[2]); nl.z = packb(al[2], bl[2]);
            nh.w = packb(ah[3], bh[3]); nl.w = packb(al[3], bl[3]);
            *(uint4*)(RNH + rp * RNP + 4 * col4) = nh;
            *(uint4*)(RNL + rp * RNP + 4 * col4) = nl;
        }
        __syncthreads();

        // ---- prefetch next tile
        if (tile + 1 < TILES) {
            const float4* Rg = (const float4*)(Rbase + (size_t)(tile + 1) * NT * Cc);
            #pragma unroll
            for (int j = 0; j < 4; j++) {
                int rp = rp0 + 16 * j;
                pfa[j] = Rg[(2 * rp) * 16 + col4];
                pfb[j] = Rg[(2 * rp + 1) * 16 + col4];
            }
        }

        // ---- Stage A: warp w rows rb..rb+15; D[n][k], 4 c-chunks of 16
        float dA[4][4];
        #pragma unroll
        for (int nb = 0; nb < 4; nb++) {
            dA[nb][0] = bias[nb][0]; dA[nb][1] = bias[nb][1];
            dA[nb][2] = bias[nb][0]; dA[nb][3] = bias[nb][1];
        }
        #pragma unroll
        for (int ch = 0; ch < 4; ch++) {
            const int cpb = 8 * ch;
            const int r0 = (rb + g) * RCP + cpb;
            const int r1 = (rb + g + 8) * RCP + cpb;
            uint32_t Ah0 = RCH[r0 + q],     Al0 = RCL[r0 + q];
            uint32_t Ah1 = RCH[r1 + q],     Al1 = RCL[r1 + q];
            uint32_t Ah2 = RCH[r0 + 4 + q], Al2 = RCL[r0 + 4 + q];
            uint32_t Ah3 = RCH[r1 + 4 + q], Al3 = RCL[r1 + 4 + q];
            #pragma unroll
            for (int nb = 0; nb < 4; nb++) {
                const int kr = (8 * nb + g) * WCP + cpb;
                uint32_t Bh0 = WCH[kr + q], Bh1 = WCH[kr + 4 + q];
                uint32_t Bl0 = WCL[kr + q], Bl1 = WCL[kr + 4 + q];
                MMA_BF16(dA[nb][0],dA[nb][1],dA[nb][2],dA[nb][3],
                         Ah0,Ah1,Ah2,Ah3, Bh0,Bh1);
                MMA_BF16(dA[nb][0],dA[nb][1],dA[nb][2],dA[nb][3],
                         Ah0,Ah1,Ah2,Ah3, Bl0,Bl1);
                MMA_BF16(dA[nb][0],dA[nb][1],dA[nb][2],dA[nb][3],
                         Al0,Al1,Al2,Al3, Bh0,Bh1);
            }
        }

        // ---- softmax over k (rows rb+g, rb+g+8)
        float mx0 = -1e30f, mx1 = -1e30f;
        #pragma unroll
        for (int nb = 0; nb < 4; nb++) {
            mx0 = fmaxf(mx0, fmaxf(dA[nb][0], dA[nb][1]));
            mx1 = fmaxf(mx1, fmaxf(dA[nb][2], dA[nb][3]));
        }
        mx0 = fmaxf(mx0, __shfl_xor_sync(0xffffffffu, mx0, 1));
        mx0 = fmaxf(mx0, __shfl_xor_sync(0xffffffffu, mx0, 2));
        mx1 = fmaxf(mx1, __shfl_xor_sync(0xffffffffu, mx1, 1));
        mx1 = fmaxf(mx1, __shfl_xor_sync(0xffffffffu, mx1, 2));
        float s0 = 0.f, s1 = 0.f;
        #pragma unroll
        for (int nb = 0; nb < 4; nb++) {
            dA[nb][0] = __expf(dA[nb][0] - mx0);
            dA[nb][1] = __expf(dA[nb][1] - mx0);
            dA[nb][2] = __expf(dA[nb][2] - mx1);
            dA[nb][3] = __expf(dA[nb][3] - mx1);
            s0 += dA[nb][0] + dA[nb][1];
            s1 += dA[nb][2] + dA[nb][3];
        }
        s0 += __shfl_xor_sync(0xffffffffu, s0, 1);
        s0 += __shfl_xor_sync(0xffffffffu, s0, 2);
        s1 += __shfl_xor_sync(0xffffffffu, s1, 1);
        s1 += __shfl_xor_sync(0xffffffffu, s1, 2);
        const float inv0 = __fdividef(1.f, s0);
        const float inv1 = __fdividef(1.f, s1);
        // pack A' over n: own (even n) + partner lane g^1 (odd n)
        #pragma unroll
        for (int nb = 0; nb < 4; nb++) {
            #pragma unroll
            for (int j = 0; j < 2; j++) {
                const int k = 8 * nb + 2 * q + j;
                float p0 = dA[nb][j]     * inv0;
                float p1 = dA[nb][j + 2] * inv1;
                asl[nb][j] += p0 + p1;
                uint32_t h0, l0, h1, l1;
                splitb(p0, h0, l0);
                splitb(p1, h1, l1);
                uint32_t ph0 = __shfl_xor_sync(0xffffffffu, h0, 4);
                uint32_t pl0 = __shfl_xor_sync(0xffffffffu, l0, 4);
                uint32_t ph1 = __shfl_xor_sync(0xffffffffu, h1, 4);
                uint32_t pl1 = __shfl_xor_sync(0xffffffffu, l1, 4);
                if (evenlane) {
                    const int np0 = (rb + g) >> 1;
                    const int np1 = (rb + g + 8) >> 1;
                    AKH[k * AKP + np0] = packb(h0, ph0);
                    AKL[k * AKP + np0] = packb(l0, pl0);
                    AKH[k * AKP + np1] = packb(h1, ph1);
                    AKL[k * AKP + np1] = packb(l1, pl1);
                }
            }
        }
        __syncthreads();   // A' visible

        // ---- Stage B: D[k][c] += A'[k][n]*R[n][c]; 8 n-chunks of 16
        #pragma unroll 4
        for (int ch = 0; ch < 8; ch++) {
            const int npb = 8 * ch;
            const int a0i = (16 * kb + g) * AKP + npb;
            const int a1i = (16 * kb + g + 8) * AKP + npb;
            uint32_t Ph0 = AKH[a0i + q],     Pl0 = AKL[a0i + q];
            uint32_t Ph1 = AKH[a1i + q],     Pl1 = AKL[a1i + q];
            uint32_t Ph2 = AKH[a0i + 4 + q], Pl2 = AKL[a0i + 4 + q];
            uint32_t Ph3 = AKH[a1i + 4 + q], Pl3 = AKL[a1i + 4 + q];
            #pragma unroll
            for (int cb = 0; cb < 2; cb++) {
                const int c0 = cb0 + 8 * cb;
                const int b0i = (npb + q) * RNP + c0 + g;
                const int b1i = (npb + 4 + q) * RNP + c0 + g;
                uint32_t Rh0 = RNH[b0i], Rl0 = RNL[b0i];
                uint32_t Rh1 = RNH[b1i], Rl1 = RNL[b1i];
                MMA_BF16(vA[cb][0],vA[cb][1],vA[cb][2],vA[cb][3],
                         Ph0,Ph1,Ph2,Ph3, Rh0,Rh1);
                MMA_BF16(vA[cb][0],vA[cb][1],vA[cb][2],vA[cb][3],
                         Ph0,Ph1,Ph2,Ph3, Rl0,Rl1);
                MMA_BF16(vA[cb][0],vA[cb][1],vA[cb][2],vA[cb][3],
                         Pl0,Pl1,Pl2,Pl3, Rh0,Rh1);
            }
        }
    }

    // ---- asum reduce + epilogue (same as R5)
    #pragma unroll
    for (int nb = 0; nb < 4; nb++) {
        #pragma unroll
        for (int j = 0; j < 2; j++) {
            float v = asl[nb][j];
            v += __shfl_xor_sync(0xffffffffu, v, 4);
            v += __shfl_xor_sync(0xffffffffu, v, 8);
            v += __shfl_xor_sync(0xffffffffu, v, 16);
            if (g == 0) atomicAdd(&asum_sm[8 * nb + 2 * q + j], v);
        }
    }
    __syncthreads();

    float* outm = out + (size_t)m * Kk * Cc;
    const int k0 = 16 * kb + g, k1 = k0 + 8;
    const float as0 = asum_sm[k0], as1 = asum_sm[k1];
    #pragma unroll
    for (int cb = 0; cb < 2; cb++) {
        const int c = cb0 + 8 * cb + 2 * q;
        const float2 c0v = *(const float2*)(cent + k0 * 64 + c);
        const float2 c1v = *(const float2*)(cent + k1 * 64 + c);
        atomicAdd(outm + k0 * 64 + c,     vA[cb][0] - as0 * c0v.x);
        atomicAdd(outm + k0 * 64 + c + 1, vA[cb][1] - as0 * c0v.y);
        atomicAdd(outm + k1 * 64 + c,     vA[cb][2] - as1 * c1v.x);
        atomicAdd(outm + k1 * 64 + c + 1, vA[cb][3] - as1 * c1v.y);
    }
}

extern "C" void kernel_launch(void* const* d_in, const int* in_sizes, int n_in,
                              void* d_out, int out_size) {
    const float* R    = (const float*)d_in[0];
    const float* W    = (const float*)d_in[1];
    const float* b    = (const float*)d_in[2];
    const float* cent = (const float*)d_in[3];
    float* out = (float*)d_out;

    cudaFuncSetAttribute(nv_tc, cudaFuncAttributeMaxDynamicSharedMemorySize, SMEM_BYTES);
    int n4 = out_size / 4;
    nv_zero<<<(n4 + 255) / 256, 256>>>((float4*)out, n4);
    nv_tc<<<256 * SPLIT, 256, SMEM_BYTES>>>(R, W, b, cent, out);
}